// round 2
// baseline (speedup 1.0000x reference)
#include <cuda_runtime.h>
#include <math.h>

// Problem constants
#define BB    4
#define DIM   192
#define HEADS 6
#define CPH   32          // channels per head
#define HH    256
#define WW    256
#define HW    65536       // H*W
#define TDIM  576         // 3*DIM

// Scratch (device globals: allocation-free contract)
// g_qkv: qkv conv output; later REUSED as attention output (192 planes/batch)
// g_dw : depthwise conv output (q,k,v read by attention)
__device__ float g_qkv[(size_t)BB * TDIM * HW];   // 604 MB
__device__ float g_dw [(size_t)BB * TDIM * HW];   // 604 MB

// ---------------------------------------------------------------------------
// 1x1 conv as GEMM: Y[b,m,n] = sum_k W[m,k] * X[b,k,n] + bias[m]
// Tiles: BM=BN=64, BK=16. 256 threads, 4x4 microtile.
// grid = (HW/64, M/64, B)
// ---------------------------------------------------------------------------
__global__ __launch_bounds__(256) void gemm1x1(
    const float* __restrict__ Wm, const float* __restrict__ bias,
    const float* __restrict__ X, float* __restrict__ Y,
    int M, int K)
{
    __shared__ float sA[16][64];   // [k][m]
    __shared__ float sB[16][64];   // [k][n]

    const int b  = blockIdx.z;
    const float* Xb = X + (size_t)b * K * HW;
    float*       Yb = Y + (size_t)b * M * HW;
    const int n0 = blockIdx.x * 64;
    const int m0 = blockIdx.y * 64;
    const int tid = threadIdx.x;
    const int tx = tid & 15, ty = tid >> 4;

    float acc[4][4] = {};

    for (int k0 = 0; k0 < K; k0 += 16) {
        // load A tile (64x16) transposed into sA[k][m]; float4 along k
        {
            int m  = tid >> 2;
            int kk = (tid & 3) * 4;
            float4 a4 = *reinterpret_cast<const float4*>(
                &Wm[(size_t)(m0 + m) * K + k0 + kk]);
            sA[kk + 0][m] = a4.x;
            sA[kk + 1][m] = a4.y;
            sA[kk + 2][m] = a4.z;
            sA[kk + 3][m] = a4.w;
        }
        // load B tile (16x64); float4 along n (coalesced)
        {
            int kk = tid >> 4;
            int n  = (tid & 15) * 4;
            float4 b4 = *reinterpret_cast<const float4*>(
                &Xb[(size_t)(k0 + kk) * HW + n0 + n]);
            *reinterpret_cast<float4*>(&sB[kk][n]) = b4;
        }
        __syncthreads();

        #pragma unroll
        for (int kk = 0; kk < 16; kk++) {
            float a[4], c[4];
            #pragma unroll
            for (int i = 0; i < 4; i++) a[i] = sA[kk][ty * 4 + i];
            #pragma unroll
            for (int j = 0; j < 4; j++) c[j] = sB[kk][tx * 4 + j];
            #pragma unroll
            for (int i = 0; i < 4; i++)
                #pragma unroll
                for (int j = 0; j < 4; j++)
                    acc[i][j] += a[i] * c[j];
        }
        __syncthreads();
    }

    #pragma unroll
    for (int i = 0; i < 4; i++) {
        int m = m0 + ty * 4 + i;
        float bi = bias[m];
        float4 o;
        o.x = acc[i][0] + bi; o.y = acc[i][1] + bi;
        o.z = acc[i][2] + bi; o.w = acc[i][3] + bi;
        *reinterpret_cast<float4*>(&Yb[(size_t)m * HW + n0 + tx * 4]) = o;
    }
}

// ---------------------------------------------------------------------------
// Depthwise 3x3 conv, SAME padding (cross-correlation, matches jax.lax.conv)
// ---------------------------------------------------------------------------
__global__ __launch_bounds__(256) void dwconv(
    const float* __restrict__ in, const float* __restrict__ wgt,
    const float* __restrict__ bias, float* __restrict__ out)
{
    int idx = blockIdx.x * 256 + threadIdx.x;     // < BB*TDIM*HW = 150,994,944
    int wcol  = idx & 255;
    int h     = (idx >> 8) & 255;
    int plane = idx >> 16;
    int ch    = plane % TDIM;

    const float* p  = in + (size_t)plane * HW;
    const float* wt = wgt + ch * 9;

    float s = bias[ch];
    #pragma unroll
    for (int dy = -1; dy <= 1; dy++) {
        int hy = h + dy;
        if ((unsigned)hy < 256u) {
            const float* row = p + hy * 256;
            #pragma unroll
            for (int dx = -1; dx <= 1; dx++) {
                int wx = wcol + dx;
                if ((unsigned)wx < 256u)
                    s += wt[(dy + 1) * 3 + (dx + 1)] * row[wx];
            }
        }
    }
    out[idx] = s;
}

// ---------------------------------------------------------------------------
// Fused per-channel attention:
//   per slice (b, head, c): Q,K,V are (256,256) fp32 planes.
//   L2-normalize Q,K rows; S = Qn Kn^T * temp[head]; softmax rows; O = P V.
// One CTA handles 64 Q rows of one slice. grid = (768, 4), 256 threads.
// smem: sQ[64][257] | sKV[64][257] | sS[64][257]  ~193 KB
// ---------------------------------------------------------------------------
#define SROW 257
#define ATTN_SMEM (3 * 64 * SROW * sizeof(float))

__global__ __launch_bounds__(256) void attn_kernel(
    const float* __restrict__ qkv,      // g_dw: (B, 576, 256, 256)
    const float* __restrict__ temperature,
    float* __restrict__ out)            // (B, 192, 256, 256)
{
    extern __shared__ float sm[];
    float* sQ = sm;
    float* sK = sm + 64 * SROW;
    float* sS = sm + 2 * 64 * SROW;

    const int tid  = threadIdx.x;
    const int tx   = tid & 15, ty = tid >> 4;
    const int lane = tid & 31, warp = tid >> 5;

    const int slice = blockIdx.x;       // 0..767
    const int qt    = blockIdx.y;       // 0..3
    const int c     = slice % CPH;
    const int head  = (slice / CPH) % HEADS;
    const int b     = slice / (CPH * HEADS);
    const int chan  = head * CPH + c;

    const float* Qg = qkv + ((size_t)b * TDIM + chan) * HW;
    const float* Kg = qkv + ((size_t)b * TDIM + DIM + chan) * HW;
    const float* Vg = qkv + ((size_t)b * TDIM + 2 * DIM + chan) * HW;
    float*       Og = out + ((size_t)b * DIM + chan) * HW;
    const float tscale = temperature[head];
    const int q0 = qt * 64;

    // ---- load Q tile (64 rows x 256) ----
    for (int i = tid; i < 64 * 64; i += 256) {
        int r = i >> 6, c4 = (i & 63) * 4;
        float4 v = *reinterpret_cast<const float4*>(&Qg[(q0 + r) * 256 + c4]);
        float* d = &sQ[r * SROW + c4];
        d[0] = v.x; d[1] = v.y; d[2] = v.z; d[3] = v.w;
    }
    __syncthreads();

    // ---- normalize Q rows (8 rows per warp) ----
    #pragma unroll
    for (int rr = 0; rr < 8; rr++) {
        int r = warp * 8 + rr;
        float ss = 0.f;
        #pragma unroll
        for (int j = lane; j < 256; j += 32) { float v = sQ[r * SROW + j]; ss += v * v; }
        #pragma unroll
        for (int o = 16; o; o >>= 1) ss += __shfl_xor_sync(0xFFFFFFFFu, ss, o);
        float inv = 1.0f / fmaxf(sqrtf(ss), 1e-12f);
        #pragma unroll
        for (int j = lane; j < 256; j += 32) sQ[r * SROW + j] *= inv;
    }
    __syncthreads();

    // ---- S = Qn Kn^T * temp, tiled over K rows ----
    for (int yt = 0; yt < 4; yt++) {
        for (int i = tid; i < 64 * 64; i += 256) {
            int r = i >> 6, c4 = (i & 63) * 4;
            float4 v = *reinterpret_cast<const float4*>(&Kg[(yt * 64 + r) * 256 + c4]);
            float* d = &sK[r * SROW + c4];
            d[0] = v.x; d[1] = v.y; d[2] = v.z; d[3] = v.w;
        }
        __syncthreads();
        #pragma unroll
        for (int rr = 0; rr < 8; rr++) {
            int r = warp * 8 + rr;
            float ss = 0.f;
            #pragma unroll
            for (int j = lane; j < 256; j += 32) { float v = sK[r * SROW + j]; ss += v * v; }
            #pragma unroll
            for (int o = 16; o; o >>= 1) ss += __shfl_xor_sync(0xFFFFFFFFu, ss, o);
            float inv = 1.0f / fmaxf(sqrtf(ss), 1e-12f);
            #pragma unroll
            for (int j = lane; j < 256; j += 32) sK[r * SROW + j] *= inv;
        }
        __syncthreads();

        float acc[4][4] = {};
        #pragma unroll 8
        for (int w = 0; w < 256; w++) {
            float a[4], kf[4];
            #pragma unroll
            for (int i = 0; i < 4; i++) a[i]  = sQ[(ty * 4 + i) * SROW + w];
            #pragma unroll
            for (int j = 0; j < 4; j++) kf[j] = sK[(tx * 4 + j) * SROW + w];
            #pragma unroll
            for (int i = 0; i < 4; i++)
                #pragma unroll
                for (int j = 0; j < 4; j++)
                    acc[i][j] += a[i] * kf[j];
        }
        #pragma unroll
        for (int i = 0; i < 4; i++)
            #pragma unroll
            for (int j = 0; j < 4; j++)
                sS[(ty * 4 + i) * SROW + yt * 64 + tx * 4 + j] = acc[i][j] * tscale;
        __syncthreads();
    }

    // ---- softmax over rows of sS (256 cols) ----
    #pragma unroll
    for (int rr = 0; rr < 8; rr++) {
        int r = warp * 8 + rr;
        float m = -1e30f;
        #pragma unroll
        for (int j = lane; j < 256; j += 32) m = fmaxf(m, sS[r * SROW + j]);
        #pragma unroll
        for (int o = 16; o; o >>= 1) m = fmaxf(m, __shfl_xor_sync(0xFFFFFFFFu, m, o));
        float s = 0.f;
        #pragma unroll
        for (int j = lane; j < 256; j += 32) {
            float e = __expf(sS[r * SROW + j] - m);
            sS[r * SROW + j] = e;
            s += e;
        }
        #pragma unroll
        for (int o = 16; o; o >>= 1) s += __shfl_xor_sync(0xFFFFFFFFu, s, o);
        float inv = 1.0f / s;
        #pragma unroll
        for (int j = lane; j < 256; j += 32) sS[r * SROW + j] *= inv;
    }
    __syncthreads();

    // ---- O = P @ V : O held in registers (4 rows x 16 cols per thread) ----
    float o[4][16] = {};
    for (int yt = 0; yt < 4; yt++) {
        for (int i = tid; i < 64 * 64; i += 256) {
            int r = i >> 6, c4 = (i & 63) * 4;
            float4 v = *reinterpret_cast<const float4*>(&Vg[(yt * 64 + r) * 256 + c4]);
            float* d = &sK[r * SROW + c4];
            d[0] = v.x; d[1] = v.y; d[2] = v.z; d[3] = v.w;
        }
        __syncthreads();
        #pragma unroll 4
        for (int y = 0; y < 64; y++) {
            float p[4];
            #pragma unroll
            for (int i = 0; i < 4; i++) p[i] = sS[(ty * 4 + i) * SROW + yt * 64 + y];
            #pragma unroll
            for (int j = 0; j < 16; j++) {
                float v = sK[y * SROW + tx + 16 * j];
                #pragma unroll
                for (int i = 0; i < 4; i++) o[i][j] += p[i] * v;
            }
        }
        __syncthreads();
    }

    #pragma unroll
    for (int i = 0; i < 4; i++) {
        int r = q0 + ty * 4 + i;
        #pragma unroll
        for (int j = 0; j < 16; j++)
            Og[r * 256 + tx + 16 * j] = o[i][j];
    }
}

// ---------------------------------------------------------------------------
// launch
// ---------------------------------------------------------------------------
extern "C" void kernel_launch(void* const* d_in, const int* in_sizes, int n_in,
                              void* d_out, int out_size)
{
    const float* x      = (const float*)d_in[0];
    const float* qkv_w  = (const float*)d_in[1];
    const float* qkv_b  = (const float*)d_in[2];
    const float* dw_w   = (const float*)d_in[3];
    const float* dw_b   = (const float*)d_in[4];
    const float* proj_w = (const float*)d_in[5];
    const float* proj_b = (const float*)d_in[6];
    const float* temp   = (const float*)d_in[7];
    float* out = (float*)d_out;

    float *p_qkv, *p_dw;
    cudaGetSymbolAddress((void**)&p_qkv, g_qkv);
    cudaGetSymbolAddress((void**)&p_dw,  g_dw);
    float* p_att = p_qkv;   // reuse: raw qkv dead after dwconv

    cudaFuncSetAttribute(attn_kernel,
                         cudaFuncAttributeMaxDynamicSharedMemorySize,
                         (int)ATTN_SMEM);

    // 1) qkv 1x1 conv: (576 x 192) x (192 x 65536) per batch
    gemm1x1<<<dim3(HW / 64, TDIM / 64, BB), 256>>>(qkv_w, qkv_b, x, p_qkv, TDIM, DIM);

    // 2) depthwise 3x3 SAME
    dwconv<<<(BB * TDIM * HW) / 256, 256>>>(p_qkv, dw_w, dw_b, p_dw);

    // 3) fused normalize + attention + softmax + PV (writes over g_qkv)
    attn_kernel<<<dim3(BB * HEADS * CPH, 4), 256, ATTN_SMEM>>>(p_dw, temp, p_att);

    // 4) proj 1x1 conv: (192 x 192) x (192 x 65536) per batch
    gemm1x1<<<dim3(HW / 64, DIM / 64, BB), 256>>>(proj_w, proj_b, p_att, out, DIM, DIM);
}

// round 4
// speedup vs baseline: 1.6864x; 1.6864x over previous
#include <cuda_runtime.h>
#include <math.h>
#include <stdint.h>

// Problem constants
#define BB    4
#define DIM   192
#define HEADS 6
#define CPH   32
#define HW    65536
#define TDIM  576
#define KDIM  192        // inner dim of both 1x1 convs

// Scratch (device globals: allocation-free contract)
__device__ float g_qkv[(size_t)BB * TDIM * HW];   // qkv out; reused for attn out
__device__ float g_dw [(size_t)BB * TDIM * HW];   // depthwise out

// ---------------------------------------------------------------------------
// tf32 helpers
// ---------------------------------------------------------------------------
__device__ __forceinline__ uint32_t f2t(float f) {
    uint32_t u;
    asm("cvt.rna.tf32.f32 %0, %1;" : "=r"(u) : "f"(f));
    return u;
}
__device__ __forceinline__ void mma8(float* c,
    uint32_t a0, uint32_t a1, uint32_t a2, uint32_t a3,
    uint32_t b0, uint32_t b1)
{
    asm volatile(
        "mma.sync.aligned.m16n8k8.row.col.f32.tf32.tf32.f32 "
        "{%0,%1,%2,%3}, {%4,%5,%6,%7}, {%8,%9}, {%0,%1,%2,%3};"
        : "+f"(c[0]), "+f"(c[1]), "+f"(c[2]), "+f"(c[3])
        : "r"(a0), "r"(a1), "r"(a2), "r"(a3), "r"(b0), "r"(b1));
}

// ---------------------------------------------------------------------------
// 1x1 conv as tf32 MMA GEMM: Y[b,m,n] = sum_k W[m,k] X[b,k,n] + bias[m]
// BM=192 (full weight row-block in smem), BN=128, BK=16, 256 thr (8 warps).
// Warp grid 4m x 2n; warp tile 48x64 = 3 m-tiles x 8 n-tiles of m16n8k8.
// smem: sW[192][196] tf32 (150.5KB) + sX[2][16][136] tf32 (17.4KB)
// ---------------------------------------------------------------------------
#define SWST 196
#define SXST 136
#define GEMM_SMEM ((192 * SWST + 2 * 16 * SXST) * 4)
#define NIT (KDIM / 16)

__global__ __launch_bounds__(256) void gemm_tf32(
    const float* __restrict__ Wm, const float* __restrict__ bias,
    const float* __restrict__ X, float* __restrict__ Y, int M)
{
    extern __shared__ uint32_t smu[];
    uint32_t* sW = smu;                    // [192][SWST]
    uint32_t* sX = smu + 192 * SWST;       // [2][16][SXST]

    const int b  = blockIdx.z;
    const float* Xb = X + (size_t)b * KDIM * HW;
    float*       Yb = Y + (size_t)b * M * HW;
    const int n0 = blockIdx.x * 128;
    const int m0 = blockIdx.y * 192;
    const int tid  = threadIdx.x;
    const int lane = tid & 31, warp = tid >> 5;
    const int g = lane >> 2, t = lane & 3;
    const int wm = warp & 3, wn = warp >> 2;

    // X staging map: 16 rows x 32 float4; thread covers idx=tid and tid+256
    const int xr0 = tid >> 5, xc0 = (tid & 31) * 4;

    // ---- stage W block [192 x 192] as tf32 ----
    {
        const float* Wblk = Wm + (size_t)m0 * KDIM;
        for (int idx = tid; idx < 192 * 48; idx += 256) {       // float4 units
            int row = idx / 48, c4 = (idx % 48) * 4;
            float4 v = *reinterpret_cast<const float4*>(&Wblk[row * KDIM + c4]);
            uint32_t* d = &sW[row * SWST + c4];
            d[0] = f2t(v.x); d[1] = f2t(v.y); d[2] = f2t(v.z); d[3] = f2t(v.w);
        }
    }
    // ---- stage X iter 0 ----
    {
        float4 v0 = *reinterpret_cast<const float4*>(&Xb[(size_t)xr0 * HW + n0 + xc0]);
        float4 v1 = *reinterpret_cast<const float4*>(&Xb[(size_t)(xr0 + 8) * HW + n0 + xc0]);
        uint32_t* d0 = &sX[xr0 * SXST + xc0];
        uint32_t* d1 = &sX[(xr0 + 8) * SXST + xc0];
        d0[0]=f2t(v0.x); d0[1]=f2t(v0.y); d0[2]=f2t(v0.z); d0[3]=f2t(v0.w);
        d1[0]=f2t(v1.x); d1[1]=f2t(v1.y); d1[2]=f2t(v1.z); d1[3]=f2t(v1.w);
    }
    __syncthreads();

    float c[3][8][4] = {};

    for (int it = 0; it < NIT; it++) {
        const uint32_t* sXb = sX + (it & 1) * 16 * SXST;
        float4 v0, v1;
        if (it + 1 < NIT) {
            int k0n = (it + 1) * 16;
            v0 = *reinterpret_cast<const float4*>(&Xb[(size_t)(k0n + xr0) * HW + n0 + xc0]);
            v1 = *reinterpret_cast<const float4*>(&Xb[(size_t)(k0n + xr0 + 8) * HW + n0 + xc0]);
        }

        #pragma unroll
        for (int ks = 0; ks < 2; ks++) {
            const int kg = it * 16 + ks * 8;   // global k into sW
            const int kl = ks * 8;             // local k into sX
            uint32_t a[3][4];
            #pragma unroll
            for (int mt = 0; mt < 3; mt++) {
                int r = wm * 48 + mt * 16;
                a[mt][0] = sW[(r + g) * SWST + kg + t];
                a[mt][1] = sW[(r + g + 8) * SWST + kg + t];
                a[mt][2] = sW[(r + g) * SWST + kg + t + 4];
                a[mt][3] = sW[(r + g + 8) * SWST + kg + t + 4];
            }
            #pragma unroll
            for (int j = 0; j < 8; j++) {
                int n = wn * 64 + j * 8;
                uint32_t b0 = sXb[(kl + t) * SXST + n + g];
                uint32_t b1 = sXb[(kl + t + 4) * SXST + n + g];
                #pragma unroll
                for (int mt = 0; mt < 3; mt++)
                    mma8(c[mt][j], a[mt][0], a[mt][1], a[mt][2], a[mt][3], b0, b1);
            }
        }

        if (it + 1 < NIT) {
            uint32_t* d = sX + ((it + 1) & 1) * 16 * SXST;
            uint32_t* d0 = &d[xr0 * SXST + xc0];
            uint32_t* d1 = &d[(xr0 + 8) * SXST + xc0];
            d0[0]=f2t(v0.x); d0[1]=f2t(v0.y); d0[2]=f2t(v0.z); d0[3]=f2t(v0.w);
            d1[0]=f2t(v1.x); d1[1]=f2t(v1.y); d1[2]=f2t(v1.z); d1[3]=f2t(v1.w);
        }
        __syncthreads();
    }

    // ---- epilogue: bias + store ----
    #pragma unroll
    for (int mt = 0; mt < 3; mt++) {
        int r = m0 + wm * 48 + mt * 16 + g;
        float bi0 = bias[r], bi1 = bias[r + 8];
        #pragma unroll
        for (int j = 0; j < 8; j++) {
            int col = n0 + wn * 64 + j * 8 + 2 * t;
            float2 o0 = make_float2(c[mt][j][0] + bi0, c[mt][j][1] + bi0);
            float2 o1 = make_float2(c[mt][j][2] + bi1, c[mt][j][3] + bi1);
            *reinterpret_cast<float2*>(&Yb[(size_t)r * HW + col]) = o0;
            *reinterpret_cast<float2*>(&Yb[(size_t)(r + 8) * HW + col]) = o1;
        }
    }
}

// ---------------------------------------------------------------------------
// Depthwise 3x3 conv, SAME padding
// ---------------------------------------------------------------------------
__global__ __launch_bounds__(256) void dwconv(
    const float* __restrict__ in, const float* __restrict__ wgt,
    const float* __restrict__ bias, float* __restrict__ out)
{
    int idx = blockIdx.x * 256 + threadIdx.x;
    int wcol  = idx & 255;
    int h     = (idx >> 8) & 255;
    int plane = idx >> 16;
    int ch    = plane % TDIM;

    const float* p  = in + (size_t)plane * HW;
    const float* wt = wgt + ch * 9;

    float s = bias[ch];
    #pragma unroll
    for (int dy = -1; dy <= 1; dy++) {
        int hy = h + dy;
        if ((unsigned)hy < 256u) {
            const float* row = p + hy * 256;
            #pragma unroll
            for (int dx = -1; dx <= 1; dx++) {
                int wx = wcol + dx;
                if ((unsigned)wx < 256u)
                    s += wt[(dy + 1) * 3 + (dx + 1)] * row[wx];
            }
        }
    }
    out[idx] = s;
}

// ---------------------------------------------------------------------------
// Fused per-channel attention with tf32 MMA.
// One CTA: 64 Q rows of one (b,head,c) slice. grid=(768,4), 256 thr (8 warps).
// smem: sQ[64][260] | sKV[64][264] | sS[64][260]  (196 KB)
// Q/K normalized then stored as tf32 bits; V cvt at staging; P cvt after softmax.
// Warp grid 4m x 2n.
// ---------------------------------------------------------------------------
#define SQS 260
#define SVS 264
#define ATTN_SMEM ((64 * SQS + 64 * SVS + 64 * SQS) * 4)

__global__ __launch_bounds__(256) void attn_mma(
    const float* __restrict__ qkv, const float* __restrict__ temperature,
    float* __restrict__ out)
{
    extern __shared__ float sm[];
    float* sQ  = sm;                       // stride SQS
    float* sKV = sm + 64 * SQS;            // K: stride SQS, V: stride SVS
    float* sS  = sm + 64 * SQS + 64 * SVS; // stride SQS
    uint32_t* uQ  = reinterpret_cast<uint32_t*>(sQ);
    uint32_t* uKV = reinterpret_cast<uint32_t*>(sKV);
    uint32_t* uS  = reinterpret_cast<uint32_t*>(sS);

    const int tid  = threadIdx.x;
    const int lane = tid & 31, warp = tid >> 5;
    const int g = lane >> 2, t = lane & 3;
    const int wm = warp & 3, wn = warp >> 2;

    const int slice = blockIdx.x;
    const int qt    = blockIdx.y;
    const int c     = slice % CPH;
    const int head  = (slice / CPH) % HEADS;
    const int b     = slice / (CPH * HEADS);
    const int chan  = head * CPH + c;

    const float* Qg = qkv + ((size_t)b * TDIM + chan) * HW;
    const float* Kg = qkv + ((size_t)b * TDIM + DIM + chan) * HW;
    const float* Vg = qkv + ((size_t)b * TDIM + 2 * DIM + chan) * HW;
    float*       Og = out + ((size_t)b * DIM + chan) * HW;
    const float tscale = temperature[head];
    const int q0 = qt * 64;

    // ---- stage Q (fp32) ----
    for (int i = tid; i < 64 * 64; i += 256) {
        int r = i >> 6, c4 = (i & 63) * 4;
        float4 v = *reinterpret_cast<const float4*>(&Qg[(q0 + r) * 256 + c4]);
        float* d = &sQ[r * SQS + c4];
        d[0] = v.x; d[1] = v.y; d[2] = v.z; d[3] = v.w;
    }
    __syncthreads();

    // ---- normalize Q rows, write back as tf32 bits ----
    #pragma unroll
    for (int rr = 0; rr < 8; rr++) {
        int r = warp * 8 + rr;
        float ss = 0.f;
        #pragma unroll
        for (int j = lane; j < 256; j += 32) { float v = sQ[r * SQS + j]; ss += v * v; }
        #pragma unroll
        for (int o = 16; o; o >>= 1) ss += __shfl_xor_sync(0xFFFFFFFFu, ss, o);
        float inv = 1.0f / fmaxf(sqrtf(ss), 1e-12f);
        #pragma unroll
        for (int j = lane; j < 256; j += 32)
            uQ[r * SQS + j] = f2t(sQ[r * SQS + j] * inv);
    }
    __syncthreads();

    // ---- S = Qn Kn^T * temp ----
    for (int yt = 0; yt < 4; yt++) {
        for (int i = tid; i < 64 * 64; i += 256) {
            int r = i >> 6, c4 = (i & 63) * 4;
            float4 v = *reinterpret_cast<const float4*>(&Kg[(yt * 64 + r) * 256 + c4]);
            float* d = &sKV[r * SQS + c4];
            d[0] = v.x; d[1] = v.y; d[2] = v.z; d[3] = v.w;
        }
        __syncthreads();
        #pragma unroll
        for (int rr = 0; rr < 8; rr++) {
            int r = warp * 8 + rr;
            float ss = 0.f;
            #pragma unroll
            for (int j = lane; j < 256; j += 32) { float v = sKV[r * SQS + j]; ss += v * v; }
            #pragma unroll
            for (int o = 16; o; o >>= 1) ss += __shfl_xor_sync(0xFFFFFFFFu, ss, o);
            float inv = 1.0f / fmaxf(sqrtf(ss), 1e-12f);
            #pragma unroll
            for (int j = lane; j < 256; j += 32)
                uKV[r * SQS + j] = f2t(sKV[r * SQS + j] * inv);
        }
        __syncthreads();

        float cqk[4][4] = {};
        #pragma unroll 4
        for (int k0 = 0; k0 < 256; k0 += 8) {
            uint32_t a0 = uQ[(wm * 16 + g) * SQS + k0 + t];
            uint32_t a1 = uQ[(wm * 16 + g + 8) * SQS + k0 + t];
            uint32_t a2 = uQ[(wm * 16 + g) * SQS + k0 + t + 4];
            uint32_t a3 = uQ[(wm * 16 + g + 8) * SQS + k0 + t + 4];
            #pragma unroll
            for (int j = 0; j < 4; j++) {
                int n = wn * 32 + j * 8;
                uint32_t b0 = uKV[(n + g) * SQS + k0 + t];
                uint32_t b1 = uKV[(n + g) * SQS + k0 + t + 4];
                mma8(cqk[j], a0, a1, a2, a3, b0, b1);
            }
        }
        #pragma unroll
        for (int j = 0; j < 4; j++) {
            int r0  = wm * 16 + g;
            int col = yt * 64 + wn * 32 + j * 8 + 2 * t;
            sS[r0 * SQS + col]           = cqk[j][0] * tscale;
            sS[r0 * SQS + col + 1]       = cqk[j][1] * tscale;
            sS[(r0 + 8) * SQS + col]     = cqk[j][2] * tscale;
            sS[(r0 + 8) * SQS + col + 1] = cqk[j][3] * tscale;
        }
        __syncthreads();
    }

    // ---- softmax rows of sS, write back P as tf32 bits ----
    #pragma unroll
    for (int rr = 0; rr < 8; rr++) {
        int r = warp * 8 + rr;
        float m = -1e30f;
        #pragma unroll
        for (int j = lane; j < 256; j += 32) m = fmaxf(m, sS[r * SQS + j]);
        #pragma unroll
        for (int o = 16; o; o >>= 1) m = fmaxf(m, __shfl_xor_sync(0xFFFFFFFFu, m, o));
        float s = 0.f;
        #pragma unroll
        for (int j = lane; j < 256; j += 32) {
            float e = __expf(sS[r * SQS + j] - m);
            sS[r * SQS + j] = e;
            s += e;
        }
        #pragma unroll
        for (int o = 16; o; o >>= 1) s += __shfl_xor_sync(0xFFFFFFFFu, s, o);
        float inv = 1.0f / s;
        #pragma unroll
        for (int j = lane; j < 256; j += 32)
            uS[r * SQS + j] = f2t(sS[r * SQS + j] * inv);
    }
    __syncthreads();

    // ---- O = P @ V ----
    float o[16][4] = {};
    for (int yt = 0; yt < 4; yt++) {
        for (int i = tid; i < 64 * 64; i += 256) {
            int r = i >> 6, c4 = (i & 63) * 4;
            float4 v = *reinterpret_cast<const float4*>(&Vg[(yt * 64 + r) * 256 + c4]);
            uint32_t* d = &uKV[r * SVS + c4];
            d[0] = f2t(v.x); d[1] = f2t(v.y); d[2] = f2t(v.z); d[3] = f2t(v.w);
        }
        __syncthreads();

        #pragma unroll
        for (int k0 = 0; k0 < 64; k0 += 8) {
            uint32_t a0 = uS[(wm * 16 + g) * SQS + yt * 64 + k0 + t];
            uint32_t a1 = uS[(wm * 16 + g + 8) * SQS + yt * 64 + k0 + t];
            uint32_t a2 = uS[(wm * 16 + g) * SQS + yt * 64 + k0 + t + 4];
            uint32_t a3 = uS[(wm * 16 + g + 8) * SQS + yt * 64 + k0 + t + 4];
            #pragma unroll
            for (int j = 0; j < 16; j++) {
                int n = wn * 128 + j * 8;
                uint32_t b0 = uKV[(k0 + t) * SVS + n + g];
                uint32_t b1 = uKV[(k0 + t + 4) * SVS + n + g];
                mma8(o[j], a0, a1, a2, a3, b0, b1);
            }
        }
        __syncthreads();
    }

    // ---- store O ----
    {
        int r0 = q0 + wm * 16 + g;
        #pragma unroll
        for (int j = 0; j < 16; j++) {
            int col = wn * 128 + j * 8 + 2 * t;
            *reinterpret_cast<float2*>(&Og[(size_t)r0 * 256 + col]) =
                make_float2(o[j][0], o[j][1]);
            *reinterpret_cast<float2*>(&Og[(size_t)(r0 + 8) * 256 + col]) =
                make_float2(o[j][2], o[j][3]);
        }
    }
}

// ---------------------------------------------------------------------------
// launch
// ---------------------------------------------------------------------------
extern "C" void kernel_launch(void* const* d_in, const int* in_sizes, int n_in,
                              void* d_out, int out_size)
{
    const float* x      = (const float*)d_in[0];
    const float* qkv_w  = (const float*)d_in[1];
    const float* qkv_b  = (const float*)d_in[2];
    const float* dw_w   = (const float*)d_in[3];
    const float* dw_b   = (const float*)d_in[4];
    const float* proj_w = (const float*)d_in[5];
    const float* proj_b = (const float*)d_in[6];
    const float* temp   = (const float*)d_in[7];
    float* out = (float*)d_out;

    float *p_qkv, *p_dw;
    cudaGetSymbolAddress((void**)&p_qkv, g_qkv);
    cudaGetSymbolAddress((void**)&p_dw,  g_dw);
    float* p_att = p_qkv;   // reuse: raw qkv dead after dwconv

    cudaFuncSetAttribute(gemm_tf32,
                         cudaFuncAttributeMaxDynamicSharedMemorySize, GEMM_SMEM);
    cudaFuncSetAttribute(attn_mma,
                         cudaFuncAttributeMaxDynamicSharedMemorySize, ATTN_SMEM);

    // 1) qkv 1x1 conv
    gemm_tf32<<<dim3(HW / 128, TDIM / 192, BB), 256, GEMM_SMEM>>>(
        qkv_w, qkv_b, x, p_qkv, TDIM);

    // 2) depthwise 3x3 SAME
    dwconv<<<(BB * TDIM * HW) / 256, 256>>>(p_qkv, dw_w, dw_b, p_dw);

    // 3) fused normalize + attention + softmax + PV (writes over g_qkv)
    attn_mma<<<dim3(BB * HEADS * CPH, 4), 256, ATTN_SMEM>>>(p_dw, temp, p_att);

    // 4) proj 1x1 conv
    gemm_tf32<<<dim3(HW / 128, DIM / 192, BB), 256, GEMM_SMEM>>>(
        proj_w, proj_b, p_att, out, DIM);
}